// round 3
// baseline (speedup 1.0000x reference)
#include <cuda_runtime.h>
#include <math.h>

#define BSZ 256        // batch B
#define NSEQ 4096      // K*B
#define H 64
#define G4 256         // 4*H
#define ZXD 320
#define LSTM_IN 322
#define TT 50

typedef unsigned long long ull;

// packed f32x2 helpers (ptxas never auto-fuses; PTX-only path)
#define FMA2(d, a, b, c) asm("fma.rn.f32x2 %0, %1, %2, %3;" : "=l"(d) : "l"(a), "l"(b), "l"(c))
#define PACKF2(d, x, y)  asm("mov.b64 %0, {%1, %2};" : "=l"(d) : "f"(x), "f"(y))
#define UNPACKF2(x, y, d) asm("mov.b64 {%0, %1}, %2;" : "=f"(x), "=f"(y) : "l"(d))

__device__ __forceinline__ float sigf(float x) {
    return __fdividef(1.f, 1.f + __expf(-x));
}
__device__ __forceinline__ float tanh_fast(float x) {
    // tanh(x) = 1 - 2/(exp(2x)+1); saturates correctly at +/-inf
    return 1.f - __fdividef(2.f, __expf(2.f * x) + 1.f);
}

// scratch
__device__ float g_G0[NSEQ * G4];   // interleaved: [n][u*4+q]
__device__ float g_h0[NSEQ * H];
__device__ float g_c0[NSEQ * H];

// ---------------------------------------------------------------------------
// Phase 1:  [G0 | h0 | c0] = zx @ [Wih[:, :320] | Wh0 | Wc0]^T  (+ biases)
// G0 written in unit-interleaved layout: g_G0[n*256 + u*4 + q]
// ---------------------------------------------------------------------------
__global__ __launch_bounds__(256) void phase1_kernel(
    const float* __restrict__ x, const float* __restrict__ z,
    const float* __restrict__ Wih, const float* __restrict__ Wh0,
    const float* __restrict__ Wc0,
    const float* __restrict__ bih, const float* __restrict__ bhh,
    const float* __restrict__ bh0, const float* __restrict__ bc0)
{
    __shared__ float As[16][68];
    __shared__ float Ws[16][68];
    const int tid = threadIdx.x;
    const int n0 = blockIdx.x * 64;
    const int c0 = blockIdx.y * 64;
    const int tx = tid & 15, ty = tid >> 4;
    float acc[4][4] = {};

    for (int kt = 0; kt < ZXD; kt += 16) {
        #pragma unroll
        for (int i = 0; i < 4; i++) {
            int e = tid + i * 256;
            int kk = e & 15, rr = e >> 4;
            int n = n0 + rr, m = kt + kk;
            float v = (m < H) ? z[n * H + m]
                              : x[(n & (BSZ - 1)) * 256 + (m - H)];
            As[kk][rr] = v;
        }
        #pragma unroll
        for (int i = 0; i < 4; i++) {
            int e = tid + i * 256;
            int kk = e & 15, cc = e >> 4;
            int j = c0 + cc, m = kt + kk;
            float v;
            if (j < G4)          v = Wih[j * LSTM_IN + m];
            else if (j < G4 + H) v = Wh0[(j - G4) * ZXD + m];
            else                 v = Wc0[(j - G4 - H) * ZXD + m];
            Ws[kk][cc] = v;
        }
        __syncthreads();
        #pragma unroll
        for (int kk = 0; kk < 16; kk++) {
            float a[4], b[4];
            #pragma unroll
            for (int i = 0; i < 4; i++) a[i] = As[kk][ty * 4 + i];
            #pragma unroll
            for (int j = 0; j < 4; j++) b[j] = Ws[kk][tx * 4 + j];
            #pragma unroll
            for (int i = 0; i < 4; i++)
                #pragma unroll
                for (int j = 0; j < 4; j++)
                    acc[i][j] += a[i] * b[j];
        }
        __syncthreads();
    }

    #pragma unroll
    for (int i = 0; i < 4; i++) {
        int n = n0 + ty * 4 + i;
        #pragma unroll
        for (int j = 0; j < 4; j++) {
            int col = c0 + tx * 4 + j;
            float v = acc[i][j];
            if (col < G4) {
                int u = col & 63, q = col >> 6;
                g_G0[n * G4 + u * 4 + q] = v + bih[col] + bhh[col];
            }
            else if (col < G4 + H) g_h0[n * H + (col - G4)]     = v + bh0[col - G4];
            else                   g_c0[n * H + (col - G4 - H)] = v + bc0[col - G4 - H];
        }
    }
}

// ---------------------------------------------------------------------------
// Phase 2: persistent recurrence.  128 blocks x 32 seqs x 256 threads.
// lane = sequence (0..31); warp = output slice (8 warps).
// All weight reads are full-warp broadcasts; h reads are conflict-free.
// ---------------------------------------------------------------------------
#define HS_STRIDE 65
#define PO_STRIDE 97

#define SM_WG   0                       // [64][256] interleaved Whh^T
#define SM_WP   (SM_WG + 64 * 256)      // [64][96]  head weights^T
#define SM_WD   (SM_WP + 64 * 96)       // [2][256]  Wih cols 320/321, interleaved
#define SM_BH   (SM_WD + 2 * 256)       // [96]
#define SM_HS   (SM_BH + 96)            // [32][65]
#define SM_PO   (SM_HS + 32 * HS_STRIDE)// [32][97]
#define SM_C1   (SM_PO + 32 * PO_STRIDE)// [32][16]
#define SM_DDE  (SM_C1 + 32 * 16)       // [32][2]
#define SM_TOT  (SM_DDE + 64)
#define SMEM_BYTES (SM_TOT * 4)

__global__ __launch_bounds__(256, 1) void phase2_kernel(
    const float* __restrict__ inp_seqs, const float* __restrict__ pred_seqs,
    const float* __restrict__ Whh, const float* __restrict__ Wih,
    const float* __restrict__ Wpi, const float* __restrict__ bpi,
    const float* __restrict__ Wmu, const float* __restrict__ bmu,
    const float* __restrict__ Wls, const float* __restrict__ bls,
    const float* __restrict__ Wcorr, const float* __restrict__ bcorr,
    float* __restrict__ out)
{
    extern __shared__ float sm[];
    const int tid  = threadIdx.x;
    const int lane = tid & 31;          // sequence within block
    const int warp = tid >> 5;          // output slice
    const int nb   = blockIdx.x * 32;

    // ---- stage weights (once) ----
    // Wg[k][u*4+q] = Whh[(q*64+u)][k]
    for (int e = tid; e < 64 * 256; e += 256) {
        int k = e >> 8, gp = e & 255;
        int u = gp >> 2, q = gp & 3;
        sm[SM_WG + k * 256 + gp] = Whh[(q * 64 + u) * 64 + k];
    }
    // Wp[k][j] head weights transposed
    for (int e = tid; e < 64 * 96; e += 256) {
        int j = e % 96, k = e / 96;
        float v;
        if (j < 16)      v = Wpi[j * 64 + k];
        else if (j < 48) v = Wmu[(j - 16) * 64 + k];
        else if (j < 80) v = Wls[(j - 48) * 64 + k];
        else             v = Wcorr[(j - 80) * 64 + k];
        sm[SM_WP + k * 96 + j] = v;
    }
    // Wd[d][u*4+q]
    for (int e = tid; e < 512; e += 256) {
        int d = e >> 8, gp = e & 255;
        int u = gp >> 2, q = gp & 3;
        sm[SM_WD + d * 256 + gp] = Wih[(q * 64 + u) * LSTM_IN + 320 + d];
    }
    if (tid < 96) {
        int j = tid; float v;
        if (j < 16)      v = bpi[j];
        else if (j < 48) v = bmu[j - 16];
        else if (j < 80) v = bls[j - 48];
        else             v = bcorr[j - 80];
        sm[SM_BH + j] = v;
    }

    // ---- per-thread state: seq = lane, units u in [8*warp, 8*warp+8) ----
    const int n = nb + lane;
    const int u0 = warp * 8;

    ull G0p[16];
    {
        const ull* g0p = (const ull*)g_G0;
        #pragma unroll
        for (int j = 0; j < 16; j++)
            G0p[j] = g0p[n * 128 + warp * 16 + j];
    }
    float cr[8];
    #pragma unroll
    for (int i = 0; i < 8; i++) {
        cr[i] = g_c0[n * H + u0 + i];
        sm[SM_HS + lane * HS_STRIDE + u0 + i] = g_h0[n * H + u0 + i];
    }

    if (tid < 64) {
        int s = tid >> 1, d = tid & 1;
        int b = (nb + s) & (BSZ - 1);
        sm[SM_DDE + s * 2 + d] = inp_seqs[(b * 8 + 7) * 24 + 20 + d];
    }
    float lacc = 0.f;  // warp 0 only
    __syncthreads();

    const float* hrow = sm + SM_HS + lane * HS_STRIDE;

    for (int t = 1; t <= TT; t++) {
        // ---- acc = G0 + dx*Wd0 + dy*Wd1 (packed pairs) ----
        ull acc[16];
        {
            float dxv = sm[SM_DDE + lane * 2];
            float dyv = sm[SM_DDE + lane * 2 + 1];
            ull dx2, dy2;
            PACKF2(dx2, dxv, dxv);
            PACKF2(dy2, dyv, dyv);
            const ulonglong2* wd0 = (const ulonglong2*)(sm + SM_WD + warp * 32);
            const ulonglong2* wd1 = (const ulonglong2*)(sm + SM_WD + 256 + warp * 32);
            #pragma unroll
            for (int i = 0; i < 8; i++) {
                ulonglong2 a = wd0[i], b = wd1[i];
                ull t0, t1;
                FMA2(t0, dx2, a.x, G0p[2 * i]);
                FMA2(acc[2 * i], dy2, b.x, t0);
                FMA2(t1, dx2, a.y, G0p[2 * i + 1]);
                FMA2(acc[2 * i + 1], dy2, b.y, t1);
            }
        }
        // ---- gates GEMM: weight loads broadcast across the warp ----
        #pragma unroll 8
        for (int k = 0; k < 64; k++) {
            float h = hrow[k];
            ull h2; PACKF2(h2, h, h);
            const ulonglong2* wr = (const ulonglong2*)(sm + SM_WG + k * 256 + warp * 32);
            #pragma unroll
            for (int i = 0; i < 8; i++) {
                ulonglong2 w = wr[i];
                FMA2(acc[2 * i],     h2, w.x, acc[2 * i]);
                FMA2(acc[2 * i + 1], h2, w.y, acc[2 * i + 1]);
            }
        }
        __syncthreads();   // done reading Hs / Dde

        // ---- pointwise LSTM update (registers) ----
        #pragma unroll
        for (int i = 0; i < 8; i++) {
            float gi, gf, gg, go;
            UNPACKF2(gi, gf, acc[2 * i]);
            UNPACKF2(gg, go, acc[2 * i + 1]);
            float si = sigf(gi), sf = sigf(gf), so = sigf(go);
            float c = sf * cr[i] + si * tanh_fast(gg);
            cr[i] = c;
            sm[SM_HS + lane * HS_STRIDE + u0 + i] = so * tanh_fast(c);
        }
        if (t < TT && tid < 64) {
            int s = tid >> 1, d = tid & 1;
            int b = (nb + s) & (BSZ - 1);
            sm[SM_DDE + s * 2 + d] = pred_seqs[(b * TT + (t - 1)) * 24 + 20 + d];
        }
        __syncthreads();   // new Hs + next Dde visible

        // ---- heads GEMM: seq = lane, outputs j in [12*warp, 12*warp+12) ----
        {
            ull ph[6];
            const ulonglong2* bhp = (const ulonglong2*)(sm + SM_BH + warp * 12);
            ulonglong2 b0 = bhp[0], b1 = bhp[1], b2 = bhp[2];
            ph[0] = b0.x; ph[1] = b0.y; ph[2] = b1.x;
            ph[3] = b1.y; ph[4] = b2.x; ph[5] = b2.y;
            #pragma unroll 8
            for (int k = 0; k < 64; k++) {
                float h = hrow[k];
                ull h2; PACKF2(h2, h, h);
                const ulonglong2* wp = (const ulonglong2*)(sm + SM_WP + k * 96 + warp * 12);
                ulonglong2 w0 = wp[0], w1 = wp[1], w2 = wp[2];
                FMA2(ph[0], h2, w0.x, ph[0]);
                FMA2(ph[1], h2, w0.y, ph[1]);
                FMA2(ph[2], h2, w1.x, ph[2]);
                FMA2(ph[3], h2, w1.y, ph[3]);
                FMA2(ph[4], h2, w2.x, ph[4]);
                FMA2(ph[5], h2, w2.y, ph[5]);
            }
            float* po = sm + SM_PO + lane * PO_STRIDE + warp * 12;
            #pragma unroll
            for (int p = 0; p < 6; p++) {
                float a, b;
                UNPACKF2(a, b, ph[p]);
                po[2 * p] = a; po[2 * p + 1] = b;
            }
        }
        __syncthreads();   // Po visible

        // ---- GMM components: C1[s][c] = pi_c + log N_c ----
        {
            int s = tid >> 3;
            int b = (nb + s) & (BSZ - 1);
            const float* tg = &pred_seqs[(b * TT + (t - 1)) * 24 + 20];
            float txv = tg[0], tyv = tg[1];
            int cbase = (tid & 7) * 2;
            const float* pr = sm + SM_PO + s * PO_STRIDE;
            #pragma unroll
            for (int cc = 0; cc < 2; cc++) {
                int c = cbase + cc;
                float pi  = pr[c];
                float mu0 = pr[16 + 2 * c], mu1 = pr[17 + 2 * c];
                float ls0 = fminf(fmaxf(pr[48 + 2 * c], -10.f), 10.f);
                float ls1 = fminf(fmaxf(pr[49 + 2 * c], -10.f), 10.f);
                float corr = tanh_fast(pr[80 + c]);
                float dx = txv - mu0, dy = tyv - mu1;
                float z0 = dx * __expf(-ls0);
                float z1 = dy * __expf(-ls1);
                float omr  = 1.f - corr * corr;
                float quad = z0 * z0 + z1 * z1 - 2.f * corr * z0 * z1;
                float cv = -1.8378770664093453f - (ls0 + ls1)
                           - 0.5f * __logf(omr) - 0.5f * __fdividef(quad, omr);
                sm[SM_C1 + s * 16 + c] = pi + cv;
            }
        }
        __syncthreads();   // C1 visible

        // ---- logsumexp + accumulate: one thread per sequence (warp 0) ----
        if (tid < 32) {
            const float* pr = sm + SM_PO + tid * PO_STRIDE;
            const float* c1 = sm + SM_C1 + tid * 16;
            float m1 = -1e30f, m2 = -1e30f;
            #pragma unroll
            for (int c = 0; c < 16; c++) {
                m1 = fmaxf(m1, pr[c]);
                m2 = fmaxf(m2, c1[c]);
            }
            float s1 = 0.f, s2 = 0.f;
            #pragma unroll
            for (int c = 0; c < 16; c++) {
                s1 += __expf(pr[c] - m1);
                s2 += __expf(c1[c] - m2);
            }
            float lp = (m2 + __logf(s2)) - (m1 + __logf(s1));
            lacc += fminf(lp, 50.f);
        }
        // Po/C1 not rewritten until after 2+ barriers next iter -> safe
    }

    if (tid < 32) out[nb + tid] = lacc;
}

// ---------------------------------------------------------------------------
extern "C" void kernel_launch(void* const* d_in, const int* in_sizes, int n_in,
                              void* d_out, int out_size)
{
    const float* x      = (const float*)d_in[0];
    const float* z      = (const float*)d_in[1];
    const float* inps   = (const float*)d_in[2];
    const float* preds  = (const float*)d_in[3];
    const float* Wh0    = (const float*)d_in[4];
    const float* bh0    = (const float*)d_in[5];
    const float* Wc0    = (const float*)d_in[6];
    const float* bc0    = (const float*)d_in[7];
    const float* Wih    = (const float*)d_in[8];
    const float* Whh    = (const float*)d_in[9];
    const float* bih    = (const float*)d_in[10];
    const float* bhh    = (const float*)d_in[11];
    const float* Wpi    = (const float*)d_in[12];
    const float* bpi    = (const float*)d_in[13];
    const float* Wmu    = (const float*)d_in[14];
    const float* bmu    = (const float*)d_in[15];
    const float* Wls    = (const float*)d_in[16];
    const float* bls    = (const float*)d_in[17];
    const float* Wcorr  = (const float*)d_in[18];
    const float* bcorr  = (const float*)d_in[19];
    float* out = (float*)d_out;

    cudaFuncSetAttribute(phase2_kernel,
                         cudaFuncAttributeMaxDynamicSharedMemorySize, SMEM_BYTES);

    dim3 g1(NSEQ / 64, 384 / 64);
    phase1_kernel<<<g1, 256>>>(x, z, Wih, Wh0, Wc0, bih, bhh, bh0, bc0);

    phase2_kernel<<<NSEQ / 32, 256, SMEM_BYTES>>>(
        inps, preds, Whh, Wih,
        Wpi, bpi, Wmu, bmu, Wls, bls, Wcorr, bcorr, out);
}

// round 4
// speedup vs baseline: 1.2073x; 1.2073x over previous
#include <cuda_runtime.h>
#include <math.h>

#define BSZ 256        // batch B
#define NSEQ 4096      // K*B
#define H 64
#define G4 256         // 4*H
#define ZXD 320
#define LSTM_IN 322
#define TT 50

typedef unsigned long long ull;

// packed f32x2 helpers (ptxas never auto-fuses; PTX-only path)
#define FMA2(d, a, b, c) asm("fma.rn.f32x2 %0, %1, %2, %3;" : "=l"(d) : "l"(a), "l"(b), "l"(c))
#define PACKF2(d, x, y)  asm("mov.b64 %0, {%1, %2};" : "=l"(d) : "f"(x), "f"(y))
#define UNPACKF2(x, y, d) asm("mov.b64 {%0, %1}, %2;" : "=f"(x), "=f"(y) : "l"(d))

__device__ __forceinline__ float sigf(float x) {
    return __fdividef(1.f, 1.f + __expf(-x));
}
__device__ __forceinline__ float tanh_fast(float x) {
    return 1.f - __fdividef(2.f, __expf(2.f * x) + 1.f);
}

// scratch
__device__ float g_G0[NSEQ * G4];   // interleaved: [n][u*4 + q]  (pair halves: q=2h,2h+1)
__device__ float g_h0[NSEQ * H];
__device__ float g_c0[NSEQ * H];

// ---------------------------------------------------------------------------
// Phase 1:  [G0 | h0 | c0] = zx @ [Wih[:, :320] | Wh0 | Wc0]^T  (+ biases)
// ---------------------------------------------------------------------------
__global__ __launch_bounds__(256) void phase1_kernel(
    const float* __restrict__ x, const float* __restrict__ z,
    const float* __restrict__ Wih, const float* __restrict__ Wh0,
    const float* __restrict__ Wc0,
    const float* __restrict__ bih, const float* __restrict__ bhh,
    const float* __restrict__ bh0, const float* __restrict__ bc0)
{
    __shared__ float As[16][68];
    __shared__ float Ws[16][68];
    const int tid = threadIdx.x;
    const int n0 = blockIdx.x * 64;
    const int c0 = blockIdx.y * 64;
    const int tx = tid & 15, ty = tid >> 4;
    float acc[4][4] = {};

    for (int kt = 0; kt < ZXD; kt += 16) {
        #pragma unroll
        for (int i = 0; i < 4; i++) {
            int e = tid + i * 256;
            int kk = e & 15, rr = e >> 4;
            int n = n0 + rr, m = kt + kk;
            float v = (m < H) ? z[n * H + m]
                              : x[(n & (BSZ - 1)) * 256 + (m - H)];
            As[kk][rr] = v;
        }
        #pragma unroll
        for (int i = 0; i < 4; i++) {
            int e = tid + i * 256;
            int kk = e & 15, cc = e >> 4;
            int j = c0 + cc, m = kt + kk;
            float v;
            if (j < G4)          v = Wih[j * LSTM_IN + m];
            else if (j < G4 + H) v = Wh0[(j - G4) * ZXD + m];
            else                 v = Wc0[(j - G4 - H) * ZXD + m];
            Ws[kk][cc] = v;
        }
        __syncthreads();
        #pragma unroll
        for (int kk = 0; kk < 16; kk++) {
            float a[4], b[4];
            #pragma unroll
            for (int i = 0; i < 4; i++) a[i] = As[kk][ty * 4 + i];
            #pragma unroll
            for (int j = 0; j < 4; j++) b[j] = Ws[kk][tx * 4 + j];
            #pragma unroll
            for (int i = 0; i < 4; i++)
                #pragma unroll
                for (int j = 0; j < 4; j++)
                    acc[i][j] += a[i] * b[j];
        }
        __syncthreads();
    }

    #pragma unroll
    for (int i = 0; i < 4; i++) {
        int n = n0 + ty * 4 + i;
        #pragma unroll
        for (int j = 0; j < 4; j++) {
            int col = c0 + tx * 4 + j;
            float v = acc[i][j];
            if (col < G4) {
                int u = col & 63, q = col >> 6;
                g_G0[n * G4 + u * 4 + q] = v + bih[col] + bhh[col];
            }
            else if (col < G4 + H) g_h0[n * H + (col - G4)]     = v + bh0[col - G4];
            else                   g_c0[n * H + (col - G4 - H)] = v + bc0[col - G4 - H];
        }
    }
}

// ---------------------------------------------------------------------------
// Phase 2: persistent recurrence.  128 blocks x 32 seqs x 256 threads.
// lane = (sg = lane>>2 [4-seq group], cg = lane&3 [col group]).
// Wavefront-dense weight loads: per k, per warp: 1 h-wf + 2 weight-wf.
// ---------------------------------------------------------------------------
#define SM_WG   0                        // [64][128 packed] gates Whh^T, 1KB rows
#define SM_WP   (SM_WG + 64 * 256)       // [64][48 packed] head weights^T, 384B rows
#define SM_HST  (SM_WP + 64 * 96)        // [64][32] h transposed, 128B rows
#define SM_PO   (SM_HST + 64 * 32)       // [32][100] head outputs
#define SM_C1   (SM_PO + 32 * 100)       // [32][16]
#define SM_DX   (SM_C1 + 32 * 16)        // [32] decode x
#define SM_DY   (SM_DX + 32)             // [32] decode y
#define SM_TOT  (SM_DY + 32)
#define SMEM_BYTES (SM_TOT * 4)

__global__ __launch_bounds__(256, 1) void phase2_kernel(
    const float* __restrict__ inp_seqs, const float* __restrict__ pred_seqs,
    const float* __restrict__ Whh, const float* __restrict__ Wih,
    const float* __restrict__ Wpi, const float* __restrict__ bpi,
    const float* __restrict__ Wmu, const float* __restrict__ bmu,
    const float* __restrict__ Wls, const float* __restrict__ bls,
    const float* __restrict__ Wcorr, const float* __restrict__ bcorr,
    float* __restrict__ out)
{
    extern __shared__ float sm[];
    const int tid  = threadIdx.x;
    const int lane = tid & 31;
    const int warp = tid >> 5;
    const int sg   = lane >> 2;       // 0..7  : seqs [4sg, 4sg+4)
    const int cg   = lane & 3;        // 0..3  : col group
    const int nb   = blockIdx.x * 32;

    // ---- stage weights ----
    // gates: Wg2[k][p] pair; p = u*2+h -> gates (q=2h, q=2h+1) of unit u
    for (int e = tid; e < 64 * 256; e += 256) {
        int k = e >> 8, col = e & 255;
        int p = col >> 1, h2i = col & 1;
        int u = p >> 1, hh = p & 1;
        sm[SM_WG + k * 256 + col] = Whh[((hh * 2 + h2i) * 64 + u) * 64 + k];
    }
    // heads: Wp2[k][j] (j = output 0..95), row 96 floats
    for (int e = tid; e < 64 * 96; e += 256) {
        int j = e % 96, k = e / 96;
        float v;
        if (j < 16)      v = Wpi[j * 64 + k];
        else if (j < 48) v = Wmu[(j - 16) * 64 + k];
        else if (j < 80) v = Wls[(j - 48) * 64 + k];
        else             v = Wcorr[(j - 80) * 64 + k];
        sm[SM_WP + k * 96 + j] = v;
    }

    // ---- register-persistent per-thread constants ----
    const int pbase = 16 * warp + 4 * cg;   // gate packed-col base
    ull WdX2[4], WdY2[4];
    #pragma unroll
    for (int pp = 0; pp < 4; pp++) {
        int p = pbase + pp;
        int u = p >> 1, hh = p & 1;
        int q0 = 2 * hh, q1 = 2 * hh + 1;
        PACKF2(WdX2[pp], Wih[(q0 * 64 + u) * LSTM_IN + 320], Wih[(q1 * 64 + u) * LSTM_IN + 320]);
        PACKF2(WdY2[pp], Wih[(q0 * 64 + u) * LSTM_IN + 321], Wih[(q1 * 64 + u) * LSTM_IN + 321]);
    }
    // head bias (warps 0..5: outputs [16w+4cg .. +4))
    ull hb0 = 0, hb1 = 0;
    if (warp < 6) {
        int j0 = 16 * warp + 4 * cg;
        const float* bsrc[4];
        float bv[4];
        #pragma unroll
        for (int jj = 0; jj < 4; jj++) {
            int j = j0 + jj;
            float v;
            if (j < 16)      v = bpi[j];
            else if (j < 48) v = bmu[j - 16];
            else if (j < 80) v = bls[j - 48];
            else             v = bcorr[j - 80];
            bv[jj] = v;
        }
        (void)bsrc;
        PACKF2(hb0, bv[0], bv[1]);
        PACKF2(hb1, bv[2], bv[3]);
    }

    // ---- state: 4 seqs x (4 packed gate cols | 2 units) ----
    ull G0p[4][4];
    float cr[4][2];
    {
        const ull* g0p = (const ull*)g_G0;
        #pragma unroll
        for (int j = 0; j < 4; j++) {
            int n = nb + 4 * sg + j;
            #pragma unroll
            for (int pp = 0; pp < 4; pp++)
                G0p[j][pp] = g0p[n * 128 + pbase + pp];
            #pragma unroll
            for (int i = 0; i < 2; i++)
                cr[j][i] = g_c0[n * H + (8 * warp + 2 * cg + i)];
        }
        // h0 -> Hs_T
        float4* HsT4w = (float4*)(sm + SM_HST);
        #pragma unroll
        for (int i = 0; i < 2; i++) {
            int u = 8 * warp + 2 * cg + i;
            float4 hv;
            hv.x = g_h0[(nb + 4 * sg + 0) * H + u];
            hv.y = g_h0[(nb + 4 * sg + 1) * H + u];
            hv.z = g_h0[(nb + 4 * sg + 2) * H + u];
            hv.w = g_h0[(nb + 4 * sg + 3) * H + u];
            HsT4w[u * 8 + sg] = hv;
        }
    }

    const int b_mine = (nb + lane) & (BSZ - 1);   // for tid<32 roles
    if (tid < 32) {
        const float* ip = inp_seqs + (b_mine * 8 + 7) * 24 + 20;
        sm[SM_DX + tid] = ip[0];
        sm[SM_DY + tid] = ip[1];
    }
    float lacc = 0.f;
    __syncthreads();

    const float4* HsT4 = (const float4*)(sm + SM_HST);
    const char* wgp = (const char*)(sm + SM_WG) + pbase * 8;
    const char* wpp = (const char*)(sm + SM_WP) + (8 * warp + 2 * cg) * 8;

    for (int t = 1; t <= TT; t++) {
        // ---- gates: acc[j][pp] = G0 + dx*WdX + dy*WdY + sum_k h[j][k]*Wg ----
        ull acc[4][4];
        {
            float4 dx4 = *(const float4*)(sm + SM_DX + sg * 4);
            float4 dy4 = *(const float4*)(sm + SM_DY + sg * 4);
            ull dx2[4], dy2[4];
            PACKF2(dx2[0], dx4.x, dx4.x); PACKF2(dx2[1], dx4.y, dx4.y);
            PACKF2(dx2[2], dx4.z, dx4.z); PACKF2(dx2[3], dx4.w, dx4.w);
            PACKF2(dy2[0], dy4.x, dy4.x); PACKF2(dy2[1], dy4.y, dy4.y);
            PACKF2(dy2[2], dy4.z, dy4.z); PACKF2(dy2[3], dy4.w, dy4.w);
            #pragma unroll
            for (int j = 0; j < 4; j++)
                #pragma unroll
                for (int pp = 0; pp < 4; pp++) {
                    ull tmp;
                    FMA2(tmp, dx2[j], WdX2[pp], G0p[j][pp]);
                    FMA2(acc[j][pp], dy2[j], WdY2[pp], tmp);
                }
        }
        #pragma unroll 4
        for (int k = 0; k < 64; k++) {
            float4 hv = HsT4[k * 8 + sg];
            ull h2[4];
            PACKF2(h2[0], hv.x, hv.x);
            PACKF2(h2[1], hv.y, hv.y);
            PACKF2(h2[2], hv.z, hv.z);
            PACKF2(h2[3], hv.w, hv.w);
            ulonglong2 wa = *(const ulonglong2*)(wgp + k * 1024);
            ulonglong2 wb = *(const ulonglong2*)(wgp + k * 1024 + 16);
            #pragma unroll
            for (int j = 0; j < 4; j++) {
                FMA2(acc[j][0], h2[j], wa.x, acc[j][0]);
                FMA2(acc[j][1], h2[j], wa.y, acc[j][1]);
                FMA2(acc[j][2], h2[j], wb.x, acc[j][2]);
                FMA2(acc[j][3], h2[j], wb.y, acc[j][3]);
            }
        }
        __syncthreads();   // Hs_T / Dde consumed

        // ---- pointwise LSTM (registers) + h store (transposed) ----
        {
            float ha[2][4];
            #pragma unroll
            for (int j = 0; j < 4; j++) {
                #pragma unroll
                for (int i = 0; i < 2; i++) {
                    float gi, gf, gg, go;
                    UNPACKF2(gi, gf, acc[j][2 * i]);
                    UNPACKF2(gg, go, acc[j][2 * i + 1]);
                    float c = sigf(gf) * cr[j][i] + sigf(gi) * tanh_fast(gg);
                    cr[j][i] = c;
                    ha[i][j] = sigf(go) * tanh_fast(c);
                }
            }
            float4* HsT4w = (float4*)(sm + SM_HST);
            #pragma unroll
            for (int i = 0; i < 2; i++) {
                int u = 8 * warp + 2 * cg + i;
                HsT4w[u * 8 + sg] = make_float4(ha[i][0], ha[i][1], ha[i][2], ha[i][3]);
            }
        }
        // prefetch decode/target row t-1 (gates t+1 AND GMM t use it)
        if (tid < 32) {
            const float* pp2 = pred_seqs + (b_mine * TT + (t - 1)) * 24 + 20;
            sm[SM_DX + tid] = pp2[0];
            sm[SM_DY + tid] = pp2[1];
        }
        __syncthreads();   // new Hs_T + Dde visible

        // ---- heads (warps 0..5): outputs [16w+4cg..+4) for 4 seqs ----
        if (warp < 6) {
            ull ph[4][2];
            #pragma unroll
            for (int j = 0; j < 4; j++) { ph[j][0] = hb0; ph[j][1] = hb1; }
            #pragma unroll 4
            for (int k = 0; k < 64; k++) {
                float4 hv = HsT4[k * 8 + sg];
                ull h2[4];
                PACKF2(h2[0], hv.x, hv.x);
                PACKF2(h2[1], hv.y, hv.y);
                PACKF2(h2[2], hv.z, hv.z);
                PACKF2(h2[3], hv.w, hv.w);
                ulonglong2 wc = *(const ulonglong2*)(wpp + k * 384);
                #pragma unroll
                for (int j = 0; j < 4; j++) {
                    FMA2(ph[j][0], h2[j], wc.x, ph[j][0]);
                    FMA2(ph[j][1], h2[j], wc.y, ph[j][1]);
                }
            }
            int j0 = 16 * warp + 4 * cg;
            #pragma unroll
            for (int j = 0; j < 4; j++) {
                float a, b, c, d;
                UNPACKF2(a, b, ph[j][0]);
                UNPACKF2(c, d, ph[j][1]);
                *(float4*)(sm + SM_PO + (4 * sg + j) * 100 + j0) = make_float4(a, b, c, d);
            }
        }
        __syncthreads();   // Po visible

        // ---- GMM components ----
        {
            int s = tid >> 3;
            float txv = sm[SM_DX + s];
            float tyv = sm[SM_DY + s];
            int cbase = (tid & 7) * 2;
            const float* pr = sm + SM_PO + s * 100;
            #pragma unroll
            for (int cc = 0; cc < 2; cc++) {
                int c = cbase + cc;
                float pi  = pr[c];
                float mu0 = pr[16 + 2 * c], mu1 = pr[17 + 2 * c];
                float ls0 = fminf(fmaxf(pr[48 + 2 * c], -10.f), 10.f);
                float ls1 = fminf(fmaxf(pr[49 + 2 * c], -10.f), 10.f);
                float corr = tanh_fast(pr[80 + c]);
                float dx = txv - mu0, dy = tyv - mu1;
                float z0 = dx * __expf(-ls0);
                float z1 = dy * __expf(-ls1);
                float omr  = 1.f - corr * corr;
                float quad = z0 * z0 + z1 * z1 - 2.f * corr * z0 * z1;
                float cv = -1.8378770664093453f - (ls0 + ls1)
                           - 0.5f * __logf(omr) - 0.5f * __fdividef(quad, omr);
                sm[SM_C1 + s * 16 + c] = pi + cv;
            }
        }
        __syncthreads();   // C1 visible

        // ---- logsumexp + accumulate (warp 0, lane = seq) ----
        if (tid < 32) {
            const float* pr = sm + SM_PO + tid * 100;
            const float* c1 = sm + SM_C1 + tid * 16;
            float m1 = -1e30f, m2 = -1e30f;
            #pragma unroll
            for (int c = 0; c < 16; c++) {
                m1 = fmaxf(m1, pr[c]);
                m2 = fmaxf(m2, c1[c]);
            }
            float s1 = 0.f, s2 = 0.f;
            #pragma unroll
            for (int c = 0; c < 16; c++) {
                s1 += __expf(pr[c] - m1);
                s2 += __expf(c1[c] - m2);
            }
            float lp = (m2 + __logf(s2)) - (m1 + __logf(s1));
            lacc += fminf(lp, 50.f);
        }
        // Po/C1 safe: rewritten only after 2+ barriers next iteration
    }

    if (tid < 32) out[nb + tid] = lacc;
}

// ---------------------------------------------------------------------------
extern "C" void kernel_launch(void* const* d_in, const int* in_sizes, int n_in,
                              void* d_out, int out_size)
{
    const float* x      = (const float*)d_in[0];
    const float* z      = (const float*)d_in[1];
    const float* inps   = (const float*)d_in[2];
    const float* preds  = (const float*)d_in[3];
    const float* Wh0    = (const float*)d_in[4];
    const float* bh0    = (const float*)d_in[5];
    const float* Wc0    = (const float*)d_in[6];
    const float* bc0    = (const float*)d_in[7];
    const float* Wih    = (const float*)d_in[8];
    const float* Whh    = (const float*)d_in[9];
    const float* bih    = (const float*)d_in[10];
    const float* bhh    = (const float*)d_in[11];
    const float* Wpi    = (const float*)d_in[12];
    const float* bpi    = (const float*)d_in[13];
    const float* Wmu    = (const float*)d_in[14];
    const float* bmu    = (const float*)d_in[15];
    const float* Wls    = (const float*)d_in[16];
    const float* bls    = (const float*)d_in[17];
    const float* Wcorr  = (const float*)d_in[18];
    const float* bcorr  = (const float*)d_in[19];
    float* out = (float*)d_out;

    cudaFuncSetAttribute(phase2_kernel,
                         cudaFuncAttributeMaxDynamicSharedMemorySize, SMEM_BYTES);

    dim3 g1(NSEQ / 64, 384 / 64);
    phase1_kernel<<<g1, 256>>>(x, z, Wih, Wh0, Wc0, bih, bhh, bh0, bc0);

    phase2_kernel<<<NSEQ / 32, 256, SMEM_BYTES>>>(
        inps, preds, Whh, Wih,
        Wpi, bpi, Wmu, bmu, Wls, bls, Wcorr, bcorr, out);
}

// round 5
// speedup vs baseline: 1.3003x; 1.0771x over previous
#include <cuda_runtime.h>
#include <math.h>

#define BSZ 256        // batch B
#define NSEQ 4096      // K*B
#define H 64
#define G4 256         // 4*H
#define ZXD 320
#define LSTM_IN 322
#define TT 50

typedef unsigned long long ull;

// packed f32x2 helpers (ptxas never auto-fuses; PTX-only path)
#define FMA2(d, a, b, c) asm("fma.rn.f32x2 %0, %1, %2, %3;" : "=l"(d) : "l"(a), "l"(b), "l"(c))
#define PACKF2(d, x, y)  asm("mov.b64 %0, {%1, %2};" : "=l"(d) : "f"(x), "f"(y))
#define UNPACKF2(x, y, d) asm("mov.b64 {%0, %1}, %2;" : "=f"(x), "=f"(y) : "l"(d))

__device__ __forceinline__ float tanhg(float x) {
    float y;
    asm("tanh.approx.f32 %0, %1;" : "=f"(y) : "f"(x));
    return y;
}
__device__ __forceinline__ float sigg(float x) {
    return fmaf(0.5f, tanhg(0.5f * x), 0.5f);
}

// scratch
__device__ float g_G0[NSEQ * G4];   // interleaved: [n][u*4 + q]
__device__ float g_h0[NSEQ * H];
__device__ float g_c0[NSEQ * H];

// ---------------------------------------------------------------------------
// Phase 1:  [G0 | h0 | c0] = zx @ [Wih[:, :320] | Wh0 | Wc0]^T  (+ biases)
// ---------------------------------------------------------------------------
__global__ __launch_bounds__(256) void phase1_kernel(
    const float* __restrict__ x, const float* __restrict__ z,
    const float* __restrict__ Wih, const float* __restrict__ Wh0,
    const float* __restrict__ Wc0,
    const float* __restrict__ bih, const float* __restrict__ bhh,
    const float* __restrict__ bh0, const float* __restrict__ bc0)
{
    __shared__ float As[16][68];
    __shared__ float Ws[16][68];
    const int tid = threadIdx.x;
    const int n0 = blockIdx.x * 64;
    const int c0 = blockIdx.y * 64;
    const int tx = tid & 15, ty = tid >> 4;
    float acc[4][4] = {};

    for (int kt = 0; kt < ZXD; kt += 16) {
        #pragma unroll
        for (int i = 0; i < 4; i++) {
            int e = tid + i * 256;
            int kk = e & 15, rr = e >> 4;
            int n = n0 + rr, m = kt + kk;
            float v = (m < H) ? z[n * H + m]
                              : x[(n & (BSZ - 1)) * 256 + (m - H)];
            As[kk][rr] = v;
        }
        #pragma unroll
        for (int i = 0; i < 4; i++) {
            int e = tid + i * 256;
            int kk = e & 15, cc = e >> 4;
            int j = c0 + cc, m = kt + kk;
            float v;
            if (j < G4)          v = Wih[j * LSTM_IN + m];
            else if (j < G4 + H) v = Wh0[(j - G4) * ZXD + m];
            else                 v = Wc0[(j - G4 - H) * ZXD + m];
            Ws[kk][cc] = v;
        }
        __syncthreads();
        #pragma unroll
        for (int kk = 0; kk < 16; kk++) {
            float a[4], b[4];
            #pragma unroll
            for (int i = 0; i < 4; i++) a[i] = As[kk][ty * 4 + i];
            #pragma unroll
            for (int j = 0; j < 4; j++) b[j] = Ws[kk][tx * 4 + j];
            #pragma unroll
            for (int i = 0; i < 4; i++)
                #pragma unroll
                for (int j = 0; j < 4; j++)
                    acc[i][j] += a[i] * b[j];
        }
        __syncthreads();
    }

    #pragma unroll
    for (int i = 0; i < 4; i++) {
        int n = n0 + ty * 4 + i;
        #pragma unroll
        for (int j = 0; j < 4; j++) {
            int col = c0 + tx * 4 + j;
            float v = acc[i][j];
            if (col < G4) {
                int u = col & 63, q = col >> 6;
                g_G0[n * G4 + u * 4 + q] = v + bih[col] + bhh[col];
            }
            else if (col < G4 + H) g_h0[n * H + (col - G4)]     = v + bh0[col - G4];
            else                   g_c0[n * H + (col - G4 - H)] = v + bc0[col - G4 - H];
        }
    }
}

// ---------------------------------------------------------------------------
// Phase 2: persistent recurrence.  128 blocks x 32 seqs x 512 threads.
// warp w (0..15) owns units [4w, 4w+4); lane = (sg = lane>>2, cg = lane&3).
// Thread: 4 seqs (4sg..4sg+3) x 1 unit (4w+cg) = 2 packed gate cols.
// ---------------------------------------------------------------------------
#define PO_STRIDE 102

#define SM_WG   0                        // [64][256] packed Whh^T, 1KB rows
#define SM_WP   (SM_WG + 64 * 256)       // [64][96]  head weights^T, 384B rows
#define SM_HST  (SM_WP + 64 * 96)        // [64][32]  h transposed, 128B rows
#define SM_PO   (SM_HST + 64 * 32)       // [32][102] head outputs
#define SM_DX   (SM_PO + 32 * PO_STRIDE) // [32] decode/target x
#define SM_DY   (SM_DX + 32)             // [32] decode/target y
#define SM_TOT  (SM_DY + 32)
#define SMEM_BYTES (SM_TOT * 4)

__global__ __launch_bounds__(512, 1) void phase2_kernel(
    const float* __restrict__ inp_seqs, const float* __restrict__ pred_seqs,
    const float* __restrict__ Whh, const float* __restrict__ Wih,
    const float* __restrict__ Wpi, const float* __restrict__ bpi,
    const float* __restrict__ Wmu, const float* __restrict__ bmu,
    const float* __restrict__ Wls, const float* __restrict__ bls,
    const float* __restrict__ Wcorr, const float* __restrict__ bcorr,
    float* __restrict__ out)
{
    extern __shared__ float sm[];
    const int tid  = threadIdx.x;
    const int lane = tid & 31;
    const int warp = tid >> 5;        // 0..15
    const int sg   = lane >> 2;       // 0..7 : seqs [4sg, 4sg+4)
    const int cg   = lane & 3;        // 0..3
    const int nb   = blockIdx.x * 32;

    // ---- stage weights ----
    // gates: Wg[k][col]; col = p*2+h2i, p = u*2+hh -> gate q = 2hh+h2i of unit u
    for (int e = tid; e < 64 * 256; e += 512) {
        int k = e >> 8, col = e & 255;
        int p = col >> 1, h2i = col & 1;
        int u = p >> 1, hh = p & 1;
        sm[SM_WG + k * 256 + col] = Whh[((hh * 2 + h2i) * 64 + u) * 64 + k];
    }
    // heads: Wp[k][j], j = output 0..95
    for (int e = tid; e < 64 * 96; e += 512) {
        int j = e % 96, k = e / 96;
        float v;
        if (j < 16)      v = Wpi[j * 64 + k];
        else if (j < 48) v = Wmu[(j - 16) * 64 + k];
        else if (j < 80) v = Wls[(j - 48) * 64 + k];
        else             v = Wcorr[(j - 80) * 64 + k];
        sm[SM_WP + k * 96 + j] = v;
    }

    // ---- per-thread constants ----
    const int pb = 8 * warp + 2 * cg;   // packed-col base (2 packed cols)
    const int u  = pb >> 1;             // unit = 4*warp + cg
    ull WdX2[2], WdY2[2];
    #pragma unroll
    for (int pp = 0; pp < 2; pp++) {
        int p = pb + pp;
        int hh = p & 1;
        int q0 = 2 * hh, q1 = 2 * hh + 1;
        PACKF2(WdX2[pp], Wih[(q0 * 64 + u) * LSTM_IN + 320], Wih[(q1 * 64 + u) * LSTM_IN + 320]);
        PACKF2(WdY2[pp], Wih[(q0 * 64 + u) * LSTM_IN + 321], Wih[(q1 * 64 + u) * LSTM_IN + 321]);
    }
    ull hb = 0;
    if (warp < 12) {
        int j0 = 8 * warp + 2 * cg;
        float bv[2];
        #pragma unroll
        for (int jj = 0; jj < 2; jj++) {
            int j = j0 + jj;
            float v;
            if (j < 16)      v = bpi[j];
            else if (j < 48) v = bmu[j - 16];
            else if (j < 80) v = bls[j - 48];
            else             v = bcorr[j - 80];
            bv[jj] = v;
        }
        PACKF2(hb, bv[0], bv[1]);
    }

    // ---- state ----
    ull G0p[4][2];
    float cr[4];
    {
        const ull* g0p = (const ull*)g_G0;
        #pragma unroll
        for (int j = 0; j < 4; j++) {
            int n = nb + 4 * sg + j;
            G0p[j][0] = g0p[n * 128 + pb];
            G0p[j][1] = g0p[n * 128 + pb + 1];
            cr[j] = g_c0[n * H + u];
        }
        float4 hv;
        hv.x = g_h0[(nb + 4 * sg + 0) * H + u];
        hv.y = g_h0[(nb + 4 * sg + 1) * H + u];
        hv.z = g_h0[(nb + 4 * sg + 2) * H + u];
        hv.w = g_h0[(nb + 4 * sg + 3) * H + u];
        ((float4*)(sm + SM_HST))[u * 8 + sg] = hv;
    }

    const int b_mine = (nb + lane) & (BSZ - 1);
    if (tid < 32) {
        const float* ip = inp_seqs + (b_mine * 8 + 7) * 24 + 20;
        sm[SM_DX + tid] = ip[0];
        sm[SM_DY + tid] = ip[1];
    }
    float lacc = 0.f;
    __syncthreads();

    const float4* HsT4 = (const float4*)(sm + SM_HST);
    const char* wgp = (const char*)(sm + SM_WG) + pb * 8;
    const char* wpp = (const char*)(sm + SM_WP) + (8 * warp + 2 * cg) * 4;

    // GMM role: warp handles seqs {2*warp, 2*warp+1}; lane = (sh, c)
    const int sh = lane >> 4;           // 0/1
    const int gc = lane & 15;           // component
    const int gs = 2 * warp + sh;       // sequence for GMM/LSE

    for (int t = 1; t <= TT; t++) {
        // ======== phase 1: gates ========
        ull acc[4][2];
        {
            float4 dx4 = *(const float4*)(sm + SM_DX + 4 * sg);
            float4 dy4 = *(const float4*)(sm + SM_DY + 4 * sg);
            float dxa[4] = {dx4.x, dx4.y, dx4.z, dx4.w};
            float dya[4] = {dy4.x, dy4.y, dy4.z, dy4.w};
            #pragma unroll
            for (int j = 0; j < 4; j++) {
                ull dx2, dy2;
                PACKF2(dx2, dxa[j], dxa[j]);
                PACKF2(dy2, dya[j], dya[j]);
                #pragma unroll
                for (int pp = 0; pp < 2; pp++) {
                    ull tmp;
                    FMA2(tmp, dx2, WdX2[pp], G0p[j][pp]);
                    FMA2(acc[j][pp], dy2, WdY2[pp], tmp);
                }
            }
        }
        #pragma unroll 4
        for (int k = 0; k < 64; k++) {
            float4 hv = HsT4[k * 8 + sg];
            ull h2[4];
            PACKF2(h2[0], hv.x, hv.x);
            PACKF2(h2[1], hv.y, hv.y);
            PACKF2(h2[2], hv.z, hv.z);
            PACKF2(h2[3], hv.w, hv.w);
            ulonglong2 w = *(const ulonglong2*)(wgp + k * 1024);
            #pragma unroll
            for (int j = 0; j < 4; j++) {
                FMA2(acc[j][0], h2[j], w.x, acc[j][0]);
                FMA2(acc[j][1], h2[j], w.y, acc[j][1]);
            }
        }
        __syncthreads();   // HsT / DX / DY consumed

        // ======== phase 2: pointwise LSTM + h store + decode prefetch ========
        {
            float ha[4];
            #pragma unroll
            for (int j = 0; j < 4; j++) {
                float gi, gf, gg, go;
                UNPACKF2(gi, gf, acc[j][0]);
                UNPACKF2(gg, go, acc[j][1]);
                float c = sigg(gf) * cr[j] + sigg(gi) * tanhg(gg);
                cr[j] = c;
                ha[j] = sigg(go) * tanhg(c);
            }
            ((float4*)(sm + SM_HST))[u * 8 + sg] = make_float4(ha[0], ha[1], ha[2], ha[3]);
        }
        if (tid < 32) {
            const float* pp2 = pred_seqs + (b_mine * TT + (t - 1)) * 24 + 20;
            sm[SM_DX + tid] = pp2[0];
            sm[SM_DY + tid] = pp2[1];
        }
        __syncthreads();   // new HsT + target row (t-1) visible

        // ======== phase 3: heads (warps 0..11) ========
        if (warp < 12) {
            ull ph[4] = {hb, hb, hb, hb};
            #pragma unroll 4
            for (int k = 0; k < 64; k++) {
                float4 hv = HsT4[k * 8 + sg];
                ull h2[4];
                PACKF2(h2[0], hv.x, hv.x);
                PACKF2(h2[1], hv.y, hv.y);
                PACKF2(h2[2], hv.z, hv.z);
                PACKF2(h2[3], hv.w, hv.w);
                ull w = *(const ull*)(wpp + k * 384);
                #pragma unroll
                for (int j = 0; j < 4; j++)
                    FMA2(ph[j], h2[j], w, ph[j]);
            }
            int j0 = 8 * warp + 2 * cg;
            #pragma unroll
            for (int j = 0; j < 4; j++) {
                float a, b;
                UNPACKF2(a, b, ph[j]);
                *(float2*)(sm + SM_PO + (4 * sg + j) * PO_STRIDE + j0) = make_float2(a, b);
            }
        }
        __syncthreads();   // Po visible

        // ======== phase 4: GMM + logsumexp (warp = 2 seqs x 16 comps) ========
        {
            float txv = sm[SM_DX + gs];
            float tyv = sm[SM_DY + gs];
            const float* pr = sm + SM_PO + gs * PO_STRIDE;
            float pi  = pr[gc];
            float2 mu = *(const float2*)(pr + 16 + 2 * gc);
            float2 lsv = *(const float2*)(pr + 48 + 2 * gc);
            float corr = tanhg(pr[80 + gc]);
            float ls0 = fminf(fmaxf(lsv.x, -10.f), 10.f);
            float ls1 = fminf(fmaxf(lsv.y, -10.f), 10.f);
            float dx = txv - mu.x, dy = tyv - mu.y;
            float z0 = dx * __expf(-ls0);
            float z1 = dy * __expf(-ls1);
            float omr  = 1.f - corr * corr;
            float quad = z0 * z0 + z1 * z1 - 2.f * corr * z0 * z1;
            float cv = -1.8378770664093453f - (ls0 + ls1)
                       - 0.5f * __logf(omr) - 0.5f * __fdividef(quad, omr);
            float a = pi + cv;       // for LSE(pi + comp)
            float b = pi;            // for LSE(pi)
            float ma = a, mb = b;
            #pragma unroll
            for (int xm = 1; xm < 16; xm <<= 1) {
                ma = fmaxf(ma, __shfl_xor_sync(0xFFFFFFFFu, ma, xm));
                mb = fmaxf(mb, __shfl_xor_sync(0xFFFFFFFFu, mb, xm));
            }
            float ea = __expf(a - ma);
            float eb = __expf(b - mb);
            #pragma unroll
            for (int xm = 1; xm < 16; xm <<= 1) {
                ea += __shfl_xor_sync(0xFFFFFFFFu, ea, xm);
                eb += __shfl_xor_sync(0xFFFFFFFFu, eb, xm);
            }
            float lp = (ma + __logf(ea)) - (mb + __logf(eb));
            lacc += fminf(lp, 50.f);
        }
        // no trailing barrier: next gates only reads HsT/DX/DY (also read here);
        // Po is next written after 2 barriers in the next iteration.
    }

    if ((lane & 15) == 0) out[nb + gs] = lacc;
}

// ---------------------------------------------------------------------------
extern "C" void kernel_launch(void* const* d_in, const int* in_sizes, int n_in,
                              void* d_out, int out_size)
{
    const float* x      = (const float*)d_in[0];
    const float* z      = (const float*)d_in[1];
    const float* inps   = (const float*)d_in[2];
    const float* preds  = (const float*)d_in[3];
    const float* Wh0    = (const float*)d_in[4];
    const float* bh0    = (const float*)d_in[5];
    const float* Wc0    = (const float*)d_in[6];
    const float* bc0    = (const float*)d_in[7];
    const float* Wih    = (const float*)d_in[8];
    const float* Whh    = (const float*)d_in[9];
    const float* bih    = (const float*)d_in[10];
    const float* bhh    = (const float*)d_in[11];
    const float* Wpi    = (const float*)d_in[12];
    const float* bpi    = (const float*)d_in[13];
    const float* Wmu    = (const float*)d_in[14];
    const float* bmu    = (const float*)d_in[15];
    const float* Wls    = (const float*)d_in[16];
    const float* bls    = (const float*)d_in[17];
    const float* Wcorr  = (const float*)d_in[18];
    const float* bcorr  = (const float*)d_in[19];
    float* out = (float*)d_out;

    cudaFuncSetAttribute(phase2_kernel,
                         cudaFuncAttributeMaxDynamicSharedMemorySize, SMEM_BYTES);

    dim3 g1(NSEQ / 64, 384 / 64);
    phase1_kernel<<<g1, 256>>>(x, z, Wih, Wh0, Wc0, bih, bhh, bh0, bc0);

    phase2_kernel<<<NSEQ / 32, 512, SMEM_BYTES>>>(
        inps, preds, Whh, Wih,
        Wpi, bpi, Wmu, bmu, Wls, bls, Wcorr, bcorr, out);
}